// round 2
// baseline (speedup 1.0000x reference)
#include <cuda_runtime.h>
#include <cuda_bf16.h>

#define NN 100000
#define EE 1600000
#define HH 64
#define CC 64
#define PP 32

// Scratch (allocation-free rule: __device__ globals)
__device__ float g_agg[(size_t)NN * HH];   // 25.6 MB
__device__ float g_deg[NN];
__device__ int   g_is64;                   // edge_index dtype flag

// ---------------------------------------------------------------------------
// Kernel 0: detect whether edge_index arrived as int64 (odd int32 words all 0)
// or int32 (odd words are random indices). Deterministic, recomputed per call.
// ---------------------------------------------------------------------------
__global__ void detect_kernel(const int* __restrict__ ei32) {
    if (threadIdx.x == 0 && blockIdx.x == 0) {
        int odd_nonzero = 0;
        for (int i = 0; i < 256; i++)
            if (ei32[2 * i + 1] != 0) odd_nonzero++;
        g_is64 = (odd_nonzero == 0) ? 1 : 0;
    }
}

// ---------------------------------------------------------------------------
// Kernel 1: zero the aggregation buffers
// ---------------------------------------------------------------------------
__global__ void zero_kernel() {
    int stride = gridDim.x * blockDim.x;
    int i = blockIdx.x * blockDim.x + threadIdx.x;
    for (int idx = i; idx < NN * HH; idx += stride) g_agg[idx] = 0.0f;
    for (int idx = i; idx < NN; idx += stride) g_deg[idx] = 0.0f;
}

// ---------------------------------------------------------------------------
// Kernel 2: edge scatter.  16 threads per edge; each thread gathers one
// float4 (16B) of x[src] (256B contiguous per edge -> coalesced) and does
// 4 scalar atomicAdds into agg[dst].  Lane 0 of each edge-group bumps deg.
// atomicAdd with unused return compiles to REDG (no round trip).
// ---------------------------------------------------------------------------
__global__ void scatter_kernel(const float4* __restrict__ x4,
                               const int* __restrict__ ei32) {
    int t = blockIdx.x * blockDim.x + threadIdx.x;
    int e = t >> 4;
    int lane = t & 15;
    if (e >= EE) return;

    int src, dst;
    if (g_is64) {   // uniform branch
        src = ei32[2 * (size_t)e];
        dst = ei32[2 * ((size_t)EE + e)];
    } else {
        src = ei32[e];
        dst = ei32[(size_t)EE + e];
    }
    if ((unsigned)src >= NN || (unsigned)dst >= NN) return;  // defensive

    float4 v = __ldg(&x4[(size_t)src * 16 + lane]);
    float* a = g_agg + (size_t)dst * HH + lane * 4;
    atomicAdd(a + 0, v.x);
    atomicAdd(a + 1, v.y);
    atomicAdd(a + 2, v.z);
    atomicAdd(a + 3, v.w);
    if (lane == 0) atomicAdd(&g_deg[dst], 1.0f);
}

// ---------------------------------------------------------------------------
// Kernel 3: fused update + prediction head.
//   x_new[n] = relu( (agg[n]/max(deg,1)) @ W + u[n] @ B + b )
//   y[n]     = x_new[n] @ Wp + bp
// W, B, Wp, biases staged in static shared memory (41 KB).
// Each thread owns one node; per-node rows streamed via float4 (L1-resident).
// Shared reads of W/B/Wp are warp-uniform -> broadcast, conflict-free.
// ---------------------------------------------------------------------------
__global__ __launch_bounds__(128) void update_kernel(
    const float* __restrict__ u,
    const float* __restrict__ W,
    const float* __restrict__ B,
    const float* __restrict__ b,
    const float* __restrict__ Wp,
    const float* __restrict__ bp,
    float* __restrict__ out) {
    __shared__ float Ws[HH * HH];      // 16 KB  W[k][j]
    __shared__ float Bs[CC * HH];      // 16 KB  B[k][j]
    __shared__ float Wps[HH * PP];     //  8 KB  Wp[j][p]
    __shared__ float bs[HH];
    __shared__ float bps[PP];

    int tid = threadIdx.x;
    for (int i = tid; i < HH * HH; i += 128) { Ws[i] = W[i]; Bs[i] = B[i]; }
    for (int i = tid; i < HH * PP; i += 128) Wps[i] = Wp[i];
    if (tid < HH) bs[tid] = b[tid];
    if (tid < PP) bps[tid] = bp[tid];
    __syncthreads();

    int n = blockIdx.x * 128 + tid;
    if (n >= NN) return;

    const float4* Ws4  = reinterpret_cast<const float4*>(Ws);
    const float4* Bs4  = reinterpret_cast<const float4*>(Bs);
    const float4* Wps4 = reinterpret_cast<const float4*>(Wps);

    float inv = 1.0f / fmaxf(g_deg[n], 1.0f);

    float acc[HH];
#pragma unroll
    for (int j = 0; j < HH; j++) acc[j] = bs[j];

    const float4* agg4 = reinterpret_cast<const float4*>(g_agg) + (size_t)n * 16;
    const float4* u4   = reinterpret_cast<const float4*>(u) + (size_t)n * 16;

#pragma unroll 1
    for (int kc = 0; kc < 16; kc++) {
        float4 m  = __ldg(&agg4[kc]);
        float4 uu = __ldg(&u4[kc]);
        float mk[4] = {m.x * inv, m.y * inv, m.z * inv, m.w * inv};
        float uk[4] = {uu.x, uu.y, uu.z, uu.w};
#pragma unroll
        for (int q = 0; q < 4; q++) {
            int k = kc * 4 + q;
#pragma unroll
            for (int j4 = 0; j4 < 16; j4++) {
                float4 w  = Ws4[k * 16 + j4];
                float4 bb = Bs4[k * 16 + j4];
                acc[j4 * 4 + 0] += mk[q] * w.x + uk[q] * bb.x;
                acc[j4 * 4 + 1] += mk[q] * w.y + uk[q] * bb.y;
                acc[j4 * 4 + 2] += mk[q] * w.z + uk[q] * bb.z;
                acc[j4 * 4 + 3] += mk[q] * w.w + uk[q] * bb.w;
            }
        }
    }

    // ReLU + write x_new
#pragma unroll
    for (int j = 0; j < HH; j++) acc[j] = fmaxf(acc[j], 0.0f);

    float4* outx4 = reinterpret_cast<float4*>(out) + (size_t)n * 16;
#pragma unroll
    for (int j4 = 0; j4 < 16; j4++)
        outx4[j4] = make_float4(acc[j4 * 4 + 0], acc[j4 * 4 + 1],
                                acc[j4 * 4 + 2], acc[j4 * 4 + 3]);

    // Prediction head: y = x_new @ Wp + bp
    float yacc[PP];
#pragma unroll
    for (int p = 0; p < PP; p++) yacc[p] = bps[p];

#pragma unroll 1
    for (int j = 0; j < HH; j++) {
        float xj = acc[j];
#pragma unroll
        for (int p4 = 0; p4 < 8; p4++) {
            float4 wp = Wps4[j * 8 + p4];
            yacc[p4 * 4 + 0] += xj * wp.x;
            yacc[p4 * 4 + 1] += xj * wp.y;
            yacc[p4 * 4 + 2] += xj * wp.z;
            yacc[p4 * 4 + 3] += xj * wp.w;
        }
    }

    float4* outy4 = reinterpret_cast<float4*>(out + (size_t)NN * HH) + (size_t)n * 8;
#pragma unroll
    for (int p4 = 0; p4 < 8; p4++)
        outy4[p4] = make_float4(yacc[p4 * 4 + 0], yacc[p4 * 4 + 1],
                                yacc[p4 * 4 + 2], yacc[p4 * 4 + 3]);
}

// ---------------------------------------------------------------------------
// Launch
// Inputs (metadata order): x, u, edge_index ([2,E], int32 or int64 — detected),
// W, B, b, Wp, bp.   Output: x_new [N*64] then y [N*32]  (float32)
// ---------------------------------------------------------------------------
extern "C" void kernel_launch(void* const* d_in, const int* in_sizes, int n_in,
                              void* d_out, int out_size) {
    const float* x       = (const float*)d_in[0];
    const float* u       = (const float*)d_in[1];
    const int*   ei32    = (const int*)d_in[2];
    const float* W       = (const float*)d_in[3];
    const float* B       = (const float*)d_in[4];
    const float* b       = (const float*)d_in[5];
    const float* Wp      = (const float*)d_in[6];
    const float* bp      = (const float*)d_in[7];
    float* out           = (float*)d_out;

    detect_kernel<<<1, 32>>>(ei32);
    zero_kernel<<<1024, 256>>>();

    long long scatter_threads = (long long)EE * 16;
    scatter_kernel<<<(int)((scatter_threads + 255) / 256), 256>>>(
        (const float4*)x, ei32);

    update_kernel<<<(NN + 127) / 128, 128>>>(u, W, B, b, Wp, bp, out);
}

// round 4
// speedup vs baseline: 2.0451x; 2.0451x over previous
#include <cuda_runtime.h>
#include <cuda_bf16.h>

#define NN 100000
#define EE 1600000
#define HH 64
#define CC 64
#define PP 32

// Scratch (allocation-free rule: __device__ globals)
__device__ float g_agg[(size_t)NN * HH];   // 25.6 MB
__device__ float g_deg[NN];
__device__ int   g_is64;                   // edge_index dtype flag

// ---------------------------------------------------------------------------
// Kernel 0: detect whether edge_index arrived as int64 (odd int32 words all 0)
// or int32 (odd words are random indices). Deterministic, recomputed per call.
// ---------------------------------------------------------------------------
__global__ void detect_kernel(const int* __restrict__ ei32) {
    if (threadIdx.x == 0 && blockIdx.x == 0) {
        int odd_nonzero = 0;
        for (int i = 0; i < 256; i++)
            if (ei32[2 * i + 1] != 0) odd_nonzero++;
        g_is64 = (odd_nonzero == 0) ? 1 : 0;
    }
}

// ---------------------------------------------------------------------------
// Kernel 1: zero agg + deg (float4 stores)
// ---------------------------------------------------------------------------
__global__ void zero_kernel() {
    int stride = gridDim.x * blockDim.x;
    int i = blockIdx.x * blockDim.x + threadIdx.x;
    float4* a4 = reinterpret_cast<float4*>(g_agg);
    const int n4 = NN * HH / 4;
    float4 z = make_float4(0.f, 0.f, 0.f, 0.f);
    for (int idx = i; idx < n4; idx += stride) a4[idx] = z;
    for (int idx = i; idx < NN; idx += stride) g_deg[idx] = 0.0f;
}

// ---------------------------------------------------------------------------
// Kernel 2: edge scatter. 16 threads/edge; each gathers one float4 of x[src]
// (256B contiguous per edge -> coalesced) and issues ONE vector atomic
// red.global.add.v4.f32 into agg[dst]. Lane 0 bumps deg.
// ---------------------------------------------------------------------------
__global__ void scatter_kernel(const float4* __restrict__ x4,
                               const int* __restrict__ ei32) {
    int t = blockIdx.x * blockDim.x + threadIdx.x;
    int e = t >> 4;
    int lane = t & 15;
    if (e >= EE) return;

    int src, dst;
    if (g_is64) {   // uniform branch
        src = ei32[2 * (size_t)e];
        dst = ei32[2 * ((size_t)EE + e)];
    } else {
        src = ei32[e];
        dst = ei32[(size_t)EE + e];
    }
    if ((unsigned)src >= NN || (unsigned)dst >= NN) return;  // defensive

    float4 v = __ldg(&x4[(size_t)src * 16 + lane]);
    float* a = g_agg + (size_t)dst * HH + lane * 4;
    asm volatile("red.global.add.v4.f32 [%0], {%1, %2, %3, %4};"
                 :: "l"(a), "f"(v.x), "f"(v.y), "f"(v.z), "f"(v.w)
                 : "memory");
    if (lane == 0) atomicAdd(&g_deg[dst], 1.0f);
}

// ---------------------------------------------------------------------------
// Kernel 3: x_new = relu(mean @ W + u @ B + b).
// 2 threads per node: thread owns a 32-wide j-half -> acc[32], no spills.
// W,B staged in smem; warp-level LDS are (near-)uniform -> broadcast.
// ---------------------------------------------------------------------------
__global__ __launch_bounds__(256) void update_kernel(
    const float* __restrict__ u,
    const float* __restrict__ W,
    const float* __restrict__ B,
    const float* __restrict__ b,
    float* __restrict__ out) {
    __shared__ float Ws[HH * HH];      // 16 KB  W[k][j]
    __shared__ float Bs[CC * HH];      // 16 KB  B[k][j]
    __shared__ float bs[HH];

    int tid = threadIdx.x;
    for (int i = tid; i < HH * HH; i += 256) { Ws[i] = W[i]; Bs[i] = B[i]; }
    if (tid < HH) bs[tid] = b[tid];
    __syncthreads();

    int n = blockIdx.x * 128 + (tid >> 1);
    int h = tid & 1;                    // j-half: [h*32, h*32+32)
    if (n >= NN) return;

    const float4* Ws4 = reinterpret_cast<const float4*>(Ws);
    const float4* Bs4 = reinterpret_cast<const float4*>(Bs);

    float inv = 1.0f / fmaxf(g_deg[n], 1.0f);

    float acc[32];
#pragma unroll
    for (int j = 0; j < 32; j++) acc[j] = bs[h * 32 + j];

    const float4* agg4 = reinterpret_cast<const float4*>(g_agg) + (size_t)n * 16;
    const float4* u4   = reinterpret_cast<const float4*>(u) + (size_t)n * 16;

#pragma unroll 1
    for (int kc = 0; kc < 16; kc++) {
        float4 m  = __ldg(&agg4[kc]);
        float4 uu = __ldg(&u4[kc]);
        float mk[4] = {m.x * inv, m.y * inv, m.z * inv, m.w * inv};
        float uk[4] = {uu.x, uu.y, uu.z, uu.w};
#pragma unroll
        for (int q = 0; q < 4; q++) {
            int k = kc * 4 + q;
            int base = k * 16 + h * 8;
#pragma unroll
            for (int j4 = 0; j4 < 8; j4++) {
                float4 w  = Ws4[base + j4];
                float4 bb = Bs4[base + j4];
                acc[j4 * 4 + 0] += mk[q] * w.x + uk[q] * bb.x;
                acc[j4 * 4 + 1] += mk[q] * w.y + uk[q] * bb.y;
                acc[j4 * 4 + 2] += mk[q] * w.z + uk[q] * bb.z;
                acc[j4 * 4 + 3] += mk[q] * w.w + uk[q] * bb.w;
            }
        }
    }

    float4* outx4 = reinterpret_cast<float4*>(out) + (size_t)n * 16 + h * 8;
#pragma unroll
    for (int j4 = 0; j4 < 8; j4++)
        outx4[j4] = make_float4(fmaxf(acc[j4 * 4 + 0], 0.f),
                                fmaxf(acc[j4 * 4 + 1], 0.f),
                                fmaxf(acc[j4 * 4 + 2], 0.f),
                                fmaxf(acc[j4 * 4 + 3], 0.f));
}

// ---------------------------------------------------------------------------
// Kernel 4: prediction head  y = x_new @ Wp + bp.
// 1 thread per node, yacc[32]; x_new read back from out (L2-hot).
// ---------------------------------------------------------------------------
__global__ __launch_bounds__(256) void head_kernel(
    const float* __restrict__ Wp,
    const float* __restrict__ bp,
    float* __restrict__ out) {
    __shared__ float Wps[HH * PP];     // 8 KB  Wp[j][p]
    __shared__ float bps[PP];

    int tid = threadIdx.x;
    for (int i = tid; i < HH * PP; i += 256) Wps[i] = Wp[i];
    if (tid < PP) bps[tid] = bp[tid];
    __syncthreads();

    int n = blockIdx.x * 256 + tid;
    if (n >= NN) return;

    const float4* Wps4 = reinterpret_cast<const float4*>(Wps);
    const float4* x4   = reinterpret_cast<const float4*>(out) + (size_t)n * 16;

    float yacc[PP];
#pragma unroll
    for (int p = 0; p < PP; p++) yacc[p] = bps[p];

#pragma unroll 1
    for (int jc = 0; jc < 16; jc++) {
        float4 xv = __ldg(&x4[jc]);
        float xs[4] = {xv.x, xv.y, xv.z, xv.w};
#pragma unroll
        for (int q = 0; q < 4; q++) {
            int j = jc * 4 + q;
#pragma unroll
            for (int p4 = 0; p4 < 8; p4++) {
                float4 wp = Wps4[j * 8 + p4];
                yacc[p4 * 4 + 0] += xs[q] * wp.x;
                yacc[p4 * 4 + 1] += xs[q] * wp.y;
                yacc[p4 * 4 + 2] += xs[q] * wp.z;
                yacc[p4 * 4 + 3] += xs[q] * wp.w;
            }
        }
    }

    float4* outy4 = reinterpret_cast<float4*>(out + (size_t)NN * HH) + (size_t)n * 8;
#pragma unroll
    for (int p4 = 0; p4 < 8; p4++)
        outy4[p4] = make_float4(yacc[p4 * 4 + 0], yacc[p4 * 4 + 1],
                                yacc[p4 * 4 + 2], yacc[p4 * 4 + 3]);
}

// ---------------------------------------------------------------------------
// Launch
// Inputs: x, u, edge_index ([2,E], int32/int64 autodetected), W, B, b, Wp, bp
// Output: x_new [N*64] then y [N*32]  (float32)
// ---------------------------------------------------------------------------
extern "C" void kernel_launch(void* const* d_in, const int* in_sizes, int n_in,
                              void* d_out, int out_size) {
    const float* x       = (const float*)d_in[0];
    const float* u       = (const float*)d_in[1];
    const int*   ei32    = (const int*)d_in[2];
    const float* W       = (const float*)d_in[3];
    const float* B       = (const float*)d_in[4];
    const float* b       = (const float*)d_in[5];
    const float* Wp      = (const float*)d_in[6];
    const float* bp      = (const float*)d_in[7];
    float* out           = (float*)d_out;

    detect_kernel<<<1, 32>>>(ei32);
    zero_kernel<<<1024, 256>>>();

    long long scatter_threads = (long long)EE * 16;
    scatter_kernel<<<(int)((scatter_threads + 255) / 256), 256>>>(
        (const float4*)x, ei32);

    update_kernel<<<(NN + 127) / 128, 256>>>(u, W, B, b, out);
    head_kernel<<<(NN + 255) / 256, 256>>>(Wp, bp, out);
}

// round 5
// speedup vs baseline: 2.5966x; 1.2697x over previous
#include <cuda_runtime.h>
#include <cuda_bf16.h>

#define NN 100000
#define EE 1600000
#define HH 64
#define CC 64
#define PP 32

// Scratch (allocation-free rule: __device__ globals)
__device__ float g_agg[(size_t)NN * HH];   // 25.6 MB
__device__ float g_deg[NN];
__device__ int   g_is64;                   // edge_index dtype flag

// ---------------------------------------------------------------------------
// Kernel 0: detect int64 vs int32 edge_index (odd int32 words all zero => i64)
// ---------------------------------------------------------------------------
__global__ void detect_kernel(const int* __restrict__ ei32) {
    if (threadIdx.x == 0 && blockIdx.x == 0) {
        int odd_nonzero = 0;
        for (int i = 0; i < 256; i++)
            if (ei32[2 * i + 1] != 0) odd_nonzero++;
        g_is64 = (odd_nonzero == 0) ? 1 : 0;
    }
}

// ---------------------------------------------------------------------------
// Kernel 1: zero agg + deg (float4 stores)
// ---------------------------------------------------------------------------
__global__ void zero_kernel() {
    int stride = gridDim.x * blockDim.x;
    int i = blockIdx.x * blockDim.x + threadIdx.x;
    float4* a4 = reinterpret_cast<float4*>(g_agg);
    const int n4 = NN * HH / 4;
    float4 z = make_float4(0.f, 0.f, 0.f, 0.f);
    for (int idx = i; idx < n4; idx += stride) a4[idx] = z;
    for (int idx = i; idx < NN; idx += stride) g_deg[idx] = 0.0f;
}

// ---------------------------------------------------------------------------
// Kernel 2: edge scatter. 8 threads/edge; each gathers TWO float4 of x[src]
// (256B contiguous per edge -> coalesced) and issues two vector atomics
// red.global.add.v4.f32 into agg[dst]. Lane 0 bumps deg.
// ---------------------------------------------------------------------------
__global__ void scatter_kernel(const float4* __restrict__ x4,
                               const int* __restrict__ ei32) {
    int t = blockIdx.x * blockDim.x + threadIdx.x;
    int e = t >> 3;
    int lane = t & 7;
    if (e >= EE) return;

    int src, dst;
    if (g_is64) {   // uniform branch
        src = ei32[2 * (size_t)e];
        dst = ei32[2 * ((size_t)EE + e)];
    } else {
        src = ei32[e];
        dst = ei32[(size_t)EE + e];
    }
    if ((unsigned)src >= NN || (unsigned)dst >= NN) return;  // defensive

    float4 v0 = __ldg(&x4[(size_t)src * 16 + lane]);
    float4 v1 = __ldg(&x4[(size_t)src * 16 + lane + 8]);
    float* a0 = g_agg + (size_t)dst * HH + lane * 4;
    float* a1 = a0 + 32;
    asm volatile("red.global.add.v4.f32 [%0], {%1, %2, %3, %4};"
                 :: "l"(a0), "f"(v0.x), "f"(v0.y), "f"(v0.z), "f"(v0.w)
                 : "memory");
    asm volatile("red.global.add.v4.f32 [%0], {%1, %2, %3, %4};"
                 :: "l"(a1), "f"(v1.x), "f"(v1.y), "f"(v1.z), "f"(v1.w)
                 : "memory");
    if (lane == 0) atomicAdd(&g_deg[dst], 1.0f);
}

// ---------------------------------------------------------------------------
// Kernel 3: x_new = relu(mean @ W + u @ B + b).
// 2 threads per node-pair axis: each thread owns a 32-wide j-half for TWO
// nodes -> every W/B shared load feeds 2x FFMA (128 FFMA : 16 LDS per q).
// __launch_bounds__(256,2) -> 128-reg budget, no spills for 64 accumulators.
// ---------------------------------------------------------------------------
__global__ __launch_bounds__(256, 2) void update_kernel(
    const float* __restrict__ u,
    const float* __restrict__ W,
    const float* __restrict__ B,
    const float* __restrict__ b,
    float* __restrict__ out) {
    __shared__ float Ws[HH * HH];      // 16 KB  W[k][j]
    __shared__ float Bs[CC * HH];      // 16 KB  B[k][j]
    __shared__ float bs[HH];

    int tid = threadIdx.x;
    for (int i = tid; i < HH * HH; i += 256) { Ws[i] = W[i]; Bs[i] = B[i]; }
    if (tid < HH) bs[tid] = b[tid];
    __syncthreads();

    int pid = tid >> 1;                 // 0..127
    int h   = tid & 1;                  // j-half: [h*32, h*32+32)
    int n0  = blockIdx.x * 256 + pid * 2;
    int n1  = n0 + 1;
    if (n0 >= NN) return;
    bool has1 = (n1 < NN);

    const float4* Ws4 = reinterpret_cast<const float4*>(Ws);
    const float4* Bs4 = reinterpret_cast<const float4*>(Bs);

    float inv0 = 1.0f / fmaxf(g_deg[n0], 1.0f);
    float inv1 = has1 ? (1.0f / fmaxf(g_deg[n1], 1.0f)) : 0.0f;

    float acc0[32], acc1[32];
#pragma unroll
    for (int j = 0; j < 32; j++) { acc0[j] = bs[h * 32 + j]; acc1[j] = acc0[j]; }

    const float4* agg4_0 = reinterpret_cast<const float4*>(g_agg) + (size_t)n0 * 16;
    const float4* u4_0   = reinterpret_cast<const float4*>(u) + (size_t)n0 * 16;
    const float4* agg4_1 = agg4_0 + (has1 ? 16 : 0);
    const float4* u4_1   = u4_0 + (has1 ? 16 : 0);

#pragma unroll 1
    for (int kc = 0; kc < 16; kc++) {
        float4 m0 = __ldg(&agg4_0[kc]);
        float4 q0 = __ldg(&u4_0[kc]);
        float4 m1 = __ldg(&agg4_1[kc]);
        float4 q1 = __ldg(&u4_1[kc]);
        float mk0[4] = {m0.x * inv0, m0.y * inv0, m0.z * inv0, m0.w * inv0};
        float uk0[4] = {q0.x, q0.y, q0.z, q0.w};
        float mk1[4] = {m1.x * inv1, m1.y * inv1, m1.z * inv1, m1.w * inv1};
        float uk1[4] = {q1.x, q1.y, q1.z, q1.w};
#pragma unroll
        for (int q = 0; q < 4; q++) {
            int base = (kc * 4 + q) * 16 + h * 8;
#pragma unroll
            for (int j4 = 0; j4 < 8; j4++) {
                float4 w  = Ws4[base + j4];
                float4 bb = Bs4[base + j4];
                acc0[j4 * 4 + 0] += mk0[q] * w.x + uk0[q] * bb.x;
                acc0[j4 * 4 + 1] += mk0[q] * w.y + uk0[q] * bb.y;
                acc0[j4 * 4 + 2] += mk0[q] * w.z + uk0[q] * bb.z;
                acc0[j4 * 4 + 3] += mk0[q] * w.w + uk0[q] * bb.w;
                acc1[j4 * 4 + 0] += mk1[q] * w.x + uk1[q] * bb.x;
                acc1[j4 * 4 + 1] += mk1[q] * w.y + uk1[q] * bb.y;
                acc1[j4 * 4 + 2] += mk1[q] * w.z + uk1[q] * bb.z;
                acc1[j4 * 4 + 3] += mk1[q] * w.w + uk1[q] * bb.w;
            }
        }
    }

    float4* outx0 = reinterpret_cast<float4*>(out) + (size_t)n0 * 16 + h * 8;
#pragma unroll
    for (int j4 = 0; j4 < 8; j4++)
        outx0[j4] = make_float4(fmaxf(acc0[j4 * 4 + 0], 0.f),
                                fmaxf(acc0[j4 * 4 + 1], 0.f),
                                fmaxf(acc0[j4 * 4 + 2], 0.f),
                                fmaxf(acc0[j4 * 4 + 3], 0.f));
    if (has1) {
        float4* outx1 = reinterpret_cast<float4*>(out) + (size_t)n1 * 16 + h * 8;
#pragma unroll
        for (int j4 = 0; j4 < 8; j4++)
            outx1[j4] = make_float4(fmaxf(acc1[j4 * 4 + 0], 0.f),
                                    fmaxf(acc1[j4 * 4 + 1], 0.f),
                                    fmaxf(acc1[j4 * 4 + 2], 0.f),
                                    fmaxf(acc1[j4 * 4 + 3], 0.f));
    }
}

// ---------------------------------------------------------------------------
// Kernel 4: prediction head  y = x_new @ Wp + bp.
// 1 thread per node, yacc[32]; x_new read back from out (L2-hot).
// ---------------------------------------------------------------------------
__global__ __launch_bounds__(256) void head_kernel(
    const float* __restrict__ Wp,
    const float* __restrict__ bp,
    float* __restrict__ out) {
    __shared__ float Wps[HH * PP];     // 8 KB  Wp[j][p]
    __shared__ float bps[PP];

    int tid = threadIdx.x;
    for (int i = tid; i < HH * PP; i += 256) Wps[i] = Wp[i];
    if (tid < PP) bps[tid] = bp[tid];
    __syncthreads();

    int n = blockIdx.x * 256 + tid;
    if (n >= NN) return;

    const float4* Wps4 = reinterpret_cast<const float4*>(Wps);
    const float4* x4   = reinterpret_cast<const float4*>(out) + (size_t)n * 16;

    float yacc[PP];
#pragma unroll
    for (int p = 0; p < PP; p++) yacc[p] = bps[p];

#pragma unroll 1
    for (int jc = 0; jc < 16; jc++) {
        float4 xv = __ldg(&x4[jc]);
        float xs[4] = {xv.x, xv.y, xv.z, xv.w};
#pragma unroll
        for (int q = 0; q < 4; q++) {
            int j = jc * 4 + q;
#pragma unroll
            for (int p4 = 0; p4 < 8; p4++) {
                float4 wp = Wps4[j * 8 + p4];
                yacc[p4 * 4 + 0] += xs[q] * wp.x;
                yacc[p4 * 4 + 1] += xs[q] * wp.y;
                yacc[p4 * 4 + 2] += xs[q] * wp.z;
                yacc[p4 * 4 + 3] += xs[q] * wp.w;
            }
        }
    }

    float4* outy4 = reinterpret_cast<float4*>(out + (size_t)NN * HH) + (size_t)n * 8;
#pragma unroll
    for (int p4 = 0; p4 < 8; p4++)
        outy4[p4] = make_float4(yacc[p4 * 4 + 0], yacc[p4 * 4 + 1],
                                yacc[p4 * 4 + 2], yacc[p4 * 4 + 3]);
}

// ---------------------------------------------------------------------------
// Launch
// Inputs: x, u, edge_index ([2,E], int32/int64 autodetected), W, B, b, Wp, bp
// Output: x_new [N*64] then y [N*32]  (float32)
// ---------------------------------------------------------------------------
extern "C" void kernel_launch(void* const* d_in, const int* in_sizes, int n_in,
                              void* d_out, int out_size) {
    const float* x       = (const float*)d_in[0];
    const float* u       = (const float*)d_in[1];
    const int*   ei32    = (const int*)d_in[2];
    const float* W       = (const float*)d_in[3];
    const float* B       = (const float*)d_in[4];
    const float* b       = (const float*)d_in[5];
    const float* Wp      = (const float*)d_in[6];
    const float* bp      = (const float*)d_in[7];
    float* out           = (float*)d_out;

    detect_kernel<<<1, 32>>>(ei32);
    zero_kernel<<<1024, 256>>>();

    long long scatter_threads = (long long)EE * 8;
    scatter_kernel<<<(int)((scatter_threads + 255) / 256), 256>>>(
        (const float4*)x, ei32);

    update_kernel<<<(NN + 255) / 256, 256>>>(u, W, B, b, out);
    head_kernel<<<(NN + 255) / 256, 256>>>(Wp, bp, out);
}